// round 3
// baseline (speedup 1.0000x reference)
#include <cuda_runtime.h>
#include <cstdint>

// Sparsemax along dim=-1 for X[4096, 32000] fp32. Persistent-CTA, chunked
// TMA ring pipeline:
//  - row lives in registers (8 x float4 per thread for t<1000; pad -inf)
//  - row split into 8 chunks of 16KB, each with its own mbarrier slot;
//    slots are consumed (1 LDS.128/thread) and re-issued immediately, so
//    the DRAM read stream always has up to 128KB in flight.
//  - store of row j interleaves with consume of row j+1 chunk-by-chunk.
//  - tau via candidate trick: support subset of {x > max-1} (~31 elems),
//    ballot compaction + warp0 Newton; block-register-Newton fallback.

#define NTHREADS 1024
#define D        32000
#define D4       8000
#define NCH      8
#define CH4      1000          // float4 per chunk
#define CHB      (CH4 * 16)    // 16000 bytes per chunk
#define CSLOTS   64            // candidate slots per warp

__device__ __forceinline__ unsigned smem_u32(const void* p) {
    return (unsigned)__cvta_generic_to_shared(p);
}

__device__ __forceinline__ float warp_max_f(float v) {
    #pragma unroll
    for (int o = 16; o > 0; o >>= 1)
        v = fmaxf(v, __shfl_xor_sync(0xffffffffu, v, o));
    return v;
}

__device__ __forceinline__ void mbar_wait(unsigned mbar, unsigned ph) {
    asm volatile(
        "{\n\t"
        ".reg .pred P;\n\t"
        "WAIT_%=: \n\t"
        "mbarrier.try_wait.parity.acquire.cta.shared::cta.b64 P, [%0], %1, 0x989680;\n\t"
        "@P bra.uni DONE_%=;\n\t"
        "bra.uni WAIT_%=;\n\t"
        "DONE_%=: \n\t"
        "}\n\t" :: "r"(mbar), "r"(ph) : "memory");
}

__device__ __forceinline__ void bulk_prefetch(unsigned dst_smem, const float* src,
                                              unsigned bytes, unsigned mbar) {
    asm volatile("mbarrier.arrive.expect_tx.shared.b64 _, [%0], %1;"
                 :: "r"(mbar), "r"(bytes) : "memory");
    asm volatile("cp.async.bulk.shared::cluster.global.mbarrier::complete_tx::bytes "
                 "[%0], [%1], %2, [%3];"
                 :: "r"(dst_smem), "l"(src), "r"(bytes), "r"(mbar) : "memory");
}

__global__ void __launch_bounds__(NTHREADS, 1)
sparsemax_kernel(const float* __restrict__ X, float* __restrict__ Y, int nrows)
{
    __shared__ float s_warpf[32];
    __shared__ int   s_warpcnt[32];
    __shared__ float s_bcast;
    __shared__ float s_tau;
    __shared__ int   s_of;
    __shared__ __align__(8) unsigned long long s_mbar[NCH];

    extern __shared__ float s_dyn[];
    float* s_ring = s_dyn;               // NCH * 4000 floats = 128000 B
    float* s_cand = s_dyn + NCH * 4000;  // 32*64 floats

    const int t    = threadIdx.x;
    const int lane = t & 31;
    const int wid  = t >> 5;
    const int grid = gridDim.x;
    const int bid  = blockIdx.x;
    const float NINF = __int_as_float(0xff800000);

    const int nrows_cta = (nrows - bid + grid - 1) / grid;   // >=1 (grid<=nrows)
    const int qmax = nrows_cta * NCH;

    if (t < NCH)
        asm volatile("mbarrier.init.shared.b64 [%0], 1;"
                     :: "r"(smem_u32(&s_mbar[t])) : "memory");
    __syncthreads();

    // issue global chunk q = jj*NCH + c  (prefetch chunk c of local row jj)
    auto issue = [&](int q) {
        if (t == 0 && q < qmax) {
            int jj = q >> 3, c = q & 7;
            long long row = bid + (long long)jj * grid;
            bulk_prefetch(smem_u32(s_ring + c * 4000),
                          X + row * (long long)D + (long long)c * (CH4 * 4),
                          CHB, smem_u32(&s_mbar[c]));
        }
    };

    // prologue: issue all chunks of row 0
    #pragma unroll
    for (int q = 0; q < NCH; q++) issue(q);

    float4 v[NCH];
    #pragma unroll
    for (int i = 0; i < NCH; i++) v[i] = make_float4(NINF, NINF, NINF, NINF);

    // consume row 0 into regs; re-issue row 1 as slots free
    #pragma unroll
    for (int c = 0; c < NCH; c++) {
        mbar_wait(smem_u32(&s_mbar[c]), 0u);
        if (t < CH4) v[c] = reinterpret_cast<const float4*>(s_ring + c * 4000)[t];
        __syncthreads();
        issue(NCH + c);
    }

    for (int j = 0; ; j++) {
        const long long row = bid + (long long)j * grid;

        // ---- block max ----------------------------------------------------
        float vmax = NINF;
        #pragma unroll
        for (int i = 0; i < NCH; i++)
            vmax = fmaxf(vmax, fmaxf(fmaxf(v[i].x, v[i].y), fmaxf(v[i].z, v[i].w)));
        float wm = warp_max_f(vmax);
        if (lane == 0) s_warpf[wid] = wm;
        if (t == 0) s_of = 0;
        __syncthreads();
        if (wid == 0) {
            float m = warp_max_f(s_warpf[lane]);
            if (lane == 0) s_bcast = m;
        }
        __syncthreads();
        const float tau0 = s_bcast - 1.0f;

        // ---- ballot compaction of candidates (x > tau0) --------------------
        {
            int cnt = 0;
            const unsigned lml = (1u << lane) - 1u;
            const int base = wid * CSLOTS;
            #pragma unroll
            for (int i = 0; i < NCH; i++) {
                float xs[4] = {v[i].x, v[i].y, v[i].z, v[i].w};
                #pragma unroll
                for (int c = 0; c < 4; c++) {
                    float x = xs[c];
                    bool p = x > tau0;
                    unsigned m = __ballot_sync(0xffffffffu, p);
                    if (p) {
                        int pos = cnt + __popc(m & lml);
                        if (pos < CSLOTS) s_cand[base + pos] = x;
                    }
                    cnt += __popc(m);
                }
            }
            if (lane == 0) { s_warpcnt[wid] = cnt; if (cnt > CSLOTS) s_of = 1; }
        }
        __syncthreads();

        // ---- warp0 Newton on candidate list --------------------------------
        if (wid == 0) {
            int n = s_warpcnt[lane]; if (n > CSLOTS) n = CSLOTS;
            const int base = lane * CSLOTS;
            float tt = tau0;
            for (int it = 0; it < 64; it++) {
                float s = 0.0f; int k = 0;
                for (int jj = 0; jj < n; jj++) {
                    float c = s_cand[base + jj];
                    if (c > tt) { s += c; k++; }
                }
                #pragma unroll
                for (int o = 16; o > 0; o >>= 1) {
                    s += __shfl_xor_sync(0xffffffffu, s, o);
                    k += __shfl_xor_sync(0xffffffffu, k, o);
                }
                float nt = (s - 1.0f) / (float)k;          // k>=1 (argmax active)
                if (nt == tt) break;
                tt = nt;
            }
            if (lane == 0) s_tau = tt;
        }
        __syncthreads();

        if (s_of) {
            // ---- fallback: block-wide Newton over registers (rare) ----------
            float tt = tau0;
            for (int it = 0; it < 64; it++) {
                float s = 0.0f; int k = 0;
                #pragma unroll
                for (int i = 0; i < NCH; i++) {
                    if (v[i].x > tt) { s += v[i].x; k++; }
                    if (v[i].y > tt) { s += v[i].y; k++; }
                    if (v[i].z > tt) { s += v[i].z; k++; }
                    if (v[i].w > tt) { s += v[i].w; k++; }
                }
                #pragma unroll
                for (int o = 16; o > 0; o >>= 1) {
                    s += __shfl_xor_sync(0xffffffffu, s, o);
                    k += __shfl_xor_sync(0xffffffffu, k, o);
                }
                if (lane == 0) { s_warpf[wid] = s; s_warpcnt[wid] = k; }
                __syncthreads();
                if (t == 0) {
                    float S = 0.0f; int K = 0;
                    #pragma unroll
                    for (int w = 0; w < 32; w++) { S += s_warpf[w]; K += s_warpcnt[w]; }
                    s_bcast = (S - 1.0f) / (float)K;
                }
                __syncthreads();
                float nt = s_bcast;
                if (nt == tt) break;                        // uniform exit
                tt = nt;
            }
            if (t == 0) s_tau = tt;
            __syncthreads();
        }
        const float tau = s_tau;

        // ---- store row j interleaved with consume of row j+1 ---------------
        const bool has_next = (j + 1) < nrows_cta;
        const unsigned nph = (unsigned)((j + 1) & 1);
        float4* dst = reinterpret_cast<float4*>(Y) + row * (long long)D4;
        #pragma unroll
        for (int c = 0; c < NCH; c++) {
            if (t < CH4) {
                float4 o;
                o.x = fmaxf(v[c].x - tau, 0.0f);
                o.y = fmaxf(v[c].y - tau, 0.0f);
                o.z = fmaxf(v[c].z - tau, 0.0f);
                o.w = fmaxf(v[c].w - tau, 0.0f);
                dst[c * CH4 + t] = o;
            }
            if (has_next) {
                mbar_wait(smem_u32(&s_mbar[c]), nph);
                if (t < CH4) v[c] = reinterpret_cast<const float4*>(s_ring + c * 4000)[t];
                __syncthreads();
                issue((j + 2) * NCH + c);
            }
        }
        if (!has_next) break;
    }
}

extern "C" void kernel_launch(void* const* d_in, const int* in_sizes, int n_in,
                              void* d_out, int out_size)
{
    const float* X = (const float*)d_in[0];
    float* Y = (float*)d_out;
    int rows = in_sizes[0] / D;                 // 4096

    int sms = 148;
    cudaDeviceGetAttribute(&sms, cudaDevAttrMultiProcessorCount, 0);
    int grid = (rows < sms) ? rows : sms;       // persistent: one CTA per SM

    size_t dyn = (size_t)(NCH * 4000 + 32 * CSLOTS) * sizeof(float);  // 136192 B
    cudaFuncSetAttribute(sparsemax_kernel,
                         cudaFuncAttributeMaxDynamicSharedMemorySize, (int)dyn);
    sparsemax_kernel<<<grid, NTHREADS, dyn>>>(X, Y, rows);
}

// round 4
// speedup vs baseline: 1.0032x; 1.0032x over previous
#include <cuda_runtime.h>
#include <cstdint>

// Sparsemax along dim=-1 for X[4096, 32000] fp32. Persistent-CTA, chunked
// TMA ring pipeline (R2 topology + continuous re-issue, stores never block):
//  - row lives in registers: v[i] = float4 at row index i*1000 + t (t<1000)
//  - 4 TMA chunks of 32KB, one mbarrier each; after copying a chunk to regs
//    (+sync) it is immediately re-issued for row j+2, so >=96KB of reads stay
//    in flight across tau-solve and stores.
//  - per row: tau-solve -> issue ALL stores -> consume loop (waits only here).
//  - tau via candidate trick: support subset of {x > max-1} (~31 elems),
//    ballot compaction + warp0 Newton; block-register-Newton fallback.

#define NTHREADS 1024
#define D        32000
#define D4       8000
#define L4       1000          // float4 per logical chunk (per reg slot)
#define NCH      4             // TMA chunks (2 logical chunks each, 32KB)
#define TCH4     2000          // float4 per TMA chunk
#define TCHB     (TCH4 * 16)   // 32000 bytes per TMA chunk
#define CSLOTS   64            // candidate slots per warp

__device__ __forceinline__ unsigned smem_u32(const void* p) {
    return (unsigned)__cvta_generic_to_shared(p);
}

__device__ __forceinline__ float warp_max_f(float v) {
    #pragma unroll
    for (int o = 16; o > 0; o >>= 1)
        v = fmaxf(v, __shfl_xor_sync(0xffffffffu, v, o));
    return v;
}

__device__ __forceinline__ void mbar_wait(unsigned mbar, unsigned ph) {
    asm volatile(
        "{\n\t"
        ".reg .pred P;\n\t"
        "WAIT_%=: \n\t"
        "mbarrier.try_wait.parity.acquire.cta.shared::cta.b64 P, [%0], %1, 0x989680;\n\t"
        "@P bra.uni DONE_%=;\n\t"
        "bra.uni WAIT_%=;\n\t"
        "DONE_%=: \n\t"
        "}\n\t" :: "r"(mbar), "r"(ph) : "memory");
}

__device__ __forceinline__ void bulk_prefetch(unsigned dst_smem, const float* src,
                                              unsigned bytes, unsigned mbar) {
    asm volatile("mbarrier.arrive.expect_tx.shared.b64 _, [%0], %1;"
                 :: "r"(mbar), "r"(bytes) : "memory");
    asm volatile("cp.async.bulk.shared::cluster.global.mbarrier::complete_tx::bytes "
                 "[%0], [%1], %2, [%3];"
                 :: "r"(dst_smem), "l"(src), "r"(bytes), "r"(mbar) : "memory");
}

__global__ void __launch_bounds__(NTHREADS, 1)
sparsemax_kernel(const float* __restrict__ X, float* __restrict__ Y, int nrows)
{
    __shared__ float s_warpf[32];
    __shared__ int   s_warpcnt[32];
    __shared__ float s_bcast;
    __shared__ float s_tau;
    __shared__ int   s_of;
    __shared__ __align__(8) unsigned long long s_mbar[NCH];

    extern __shared__ float s_dyn[];
    float* s_ring = s_dyn;               // NCH * 8000 floats = 128000 B
    float* s_cand = s_dyn + NCH * 8000;  // 32*64 floats

    const int t    = threadIdx.x;
    const int lane = t & 31;
    const int wid  = t >> 5;
    const int grid = gridDim.x;
    const int bid  = blockIdx.x;
    const float NINF = __int_as_float(0xff800000);

    const int nrows_cta = (nrows - bid + grid - 1) / grid;   // >=1 (grid<=nrows)
    const int qmax = nrows_cta * NCH;

    if (t < NCH)
        asm volatile("mbarrier.init.shared.b64 [%0], 1;"
                     :: "r"(smem_u32(&s_mbar[t])) : "memory");
    __syncthreads();

    // issue global chunk q = jj*NCH + c  (prefetch TMA chunk c of local row jj)
    auto issue = [&](int q) {
        if (t == 0 && q < qmax) {
            int jj = q >> 2, c = q & 3;
            long long row = bid + (long long)jj * grid;
            bulk_prefetch(smem_u32(s_ring + c * TCH4 * 4),
                          X + row * (long long)D + (long long)c * (TCH4 * 4),
                          TCHB, smem_u32(&s_mbar[c]));
        }
    };

    // prologue: issue all chunks of row 0
    #pragma unroll
    for (int q = 0; q < NCH; q++) issue(q);

    float4 v[8];
    #pragma unroll
    for (int i = 0; i < 8; i++) v[i] = make_float4(NINF, NINF, NINF, NINF);

    // consume row 0 into regs; re-issue row 1 as slots free
    #pragma unroll
    for (int c = 0; c < NCH; c++) {
        mbar_wait(smem_u32(&s_mbar[c]), 0u);
        if (t < L4) {
            const float4* sb4 = reinterpret_cast<const float4*>(s_ring + c * TCH4 * 4);
            v[2 * c]     = sb4[t];
            v[2 * c + 1] = sb4[L4 + t];
        }
        __syncthreads();
        issue(NCH + c);
    }

    for (int j = 0; ; j++) {
        const long long row = bid + (long long)j * grid;

        // ---- block max ----------------------------------------------------
        float vmax = NINF;
        #pragma unroll
        for (int i = 0; i < 8; i++)
            vmax = fmaxf(vmax, fmaxf(fmaxf(v[i].x, v[i].y), fmaxf(v[i].z, v[i].w)));
        float wm = warp_max_f(vmax);
        if (lane == 0) s_warpf[wid] = wm;
        if (t == 0) s_of = 0;
        __syncthreads();
        if (wid == 0) {
            float m = warp_max_f(s_warpf[lane]);
            if (lane == 0) s_bcast = m;
        }
        __syncthreads();
        const float tau0 = s_bcast - 1.0f;

        // ---- ballot compaction of candidates (x > tau0) --------------------
        {
            int cnt = 0;
            const unsigned lml = (1u << lane) - 1u;
            const int base = wid * CSLOTS;
            #pragma unroll
            for (int i = 0; i < 8; i++) {
                float xs[4] = {v[i].x, v[i].y, v[i].z, v[i].w};
                #pragma unroll
                for (int c = 0; c < 4; c++) {
                    float x = xs[c];
                    bool p = x > tau0;
                    unsigned m = __ballot_sync(0xffffffffu, p);
                    if (p) {
                        int pos = cnt + __popc(m & lml);
                        if (pos < CSLOTS) s_cand[base + pos] = x;
                    }
                    cnt += __popc(m);
                }
            }
            if (lane == 0) { s_warpcnt[wid] = cnt; if (cnt > CSLOTS) s_of = 1; }
        }
        __syncthreads();

        // ---- warp0 Newton on candidate list --------------------------------
        if (wid == 0) {
            int n = s_warpcnt[lane]; if (n > CSLOTS) n = CSLOTS;
            const int base = lane * CSLOTS;
            float tt = tau0;
            for (int it = 0; it < 64; it++) {
                float s = 0.0f; int k = 0;
                for (int jj = 0; jj < n; jj++) {
                    float c = s_cand[base + jj];
                    if (c > tt) { s += c; k++; }
                }
                #pragma unroll
                for (int o = 16; o > 0; o >>= 1) {
                    s += __shfl_xor_sync(0xffffffffu, s, o);
                    k += __shfl_xor_sync(0xffffffffu, k, o);
                }
                float nt = (s - 1.0f) / (float)k;          // k>=1 (argmax active)
                if (nt == tt) break;
                tt = nt;
            }
            if (lane == 0) s_tau = tt;
        }
        __syncthreads();

        if (s_of) {
            // ---- fallback: block-wide Newton over registers (rare) ----------
            float tt = tau0;
            for (int it = 0; it < 64; it++) {
                float s = 0.0f; int k = 0;
                #pragma unroll
                for (int i = 0; i < 8; i++) {
                    if (v[i].x > tt) { s += v[i].x; k++; }
                    if (v[i].y > tt) { s += v[i].y; k++; }
                    if (v[i].z > tt) { s += v[i].z; k++; }
                    if (v[i].w > tt) { s += v[i].w; k++; }
                }
                #pragma unroll
                for (int o = 16; o > 0; o >>= 1) {
                    s += __shfl_xor_sync(0xffffffffu, s, o);
                    k += __shfl_xor_sync(0xffffffffu, k, o);
                }
                if (lane == 0) { s_warpf[wid] = s; s_warpcnt[wid] = k; }
                __syncthreads();
                if (t == 0) {
                    float S = 0.0f; int K = 0;
                    #pragma unroll
                    for (int w = 0; w < 32; w++) { S += s_warpf[w]; K += s_warpcnt[w]; }
                    s_bcast = (S - 1.0f) / (float)K;
                }
                __syncthreads();
                float nt = s_bcast;
                if (nt == tt) break;                        // uniform exit
                tt = nt;
            }
            if (t == 0) s_tau = tt;
            __syncthreads();
        }
        const float tau = s_tau;

        // ---- issue ALL stores for row j (no waits in this phase) ------------
        if (t < L4) {
            float4* dst = reinterpret_cast<float4*>(Y) + row * (long long)D4;
            #pragma unroll
            for (int i = 0; i < 8; i++) {
                float4 o;
                o.x = fmaxf(v[i].x - tau, 0.0f);
                o.y = fmaxf(v[i].y - tau, 0.0f);
                o.z = fmaxf(v[i].z - tau, 0.0f);
                o.w = fmaxf(v[i].w - tau, 0.0f);
                dst[i * L4 + t] = o;
            }
        }

        if (j + 1 >= nrows_cta) break;

        // ---- consume row j+1, re-issue row j+2 chunk-by-chunk ---------------
        const unsigned nph = (unsigned)((j + 1) & 1);
        #pragma unroll
        for (int c = 0; c < NCH; c++) {
            mbar_wait(smem_u32(&s_mbar[c]), nph);
            if (t < L4) {
                const float4* sb4 = reinterpret_cast<const float4*>(s_ring + c * TCH4 * 4);
                v[2 * c]     = sb4[t];
                v[2 * c + 1] = sb4[L4 + t];
            }
            __syncthreads();
            issue((j + 2) * NCH + c);
        }
    }
}

extern "C" void kernel_launch(void* const* d_in, const int* in_sizes, int n_in,
                              void* d_out, int out_size)
{
    const float* X = (const float*)d_in[0];
    float* Y = (float*)d_out;
    int rows = in_sizes[0] / D;                 // 4096

    int sms = 148;
    cudaDeviceGetAttribute(&sms, cudaDevAttrMultiProcessorCount, 0);
    int grid = (rows < sms) ? rows : sms;       // persistent: one CTA per SM

    size_t dyn = (size_t)(NCH * 8000 + 32 * CSLOTS) * sizeof(float);  // 136192 B
    cudaFuncSetAttribute(sparsemax_kernel,
                         cudaFuncAttributeMaxDynamicSharedMemorySize, (int)dyn);
    sparsemax_kernel<<<grid, NTHREADS, dyn>>>(X, Y, rows);
}